// round 4
// baseline (speedup 1.0000x reference)
#include <cuda_runtime.h>
#include <cuda_bf16.h>
#include <math.h>

// Problem constants (fixed shapes)
#define NN 50000
#define EE 800000
#define ET (EE + NN)        // edges incl. self loops = 850000
#define HC 64               // heads*hid
#define F_IN 128
#define OUTD 16

// Scratch (device globals; no allocation allowed)
__device__ __align__(16) float g_xl[(size_t)NN * HC];
__device__ __align__(16) float g_xr[(size_t)NN * HC];
__device__ __align__(16) float g_h [(size_t)NN * HC];
__device__ __align__(16) float g_agg[(size_t)NN * HC];
__device__ __align__(16) float g_ex[(size_t)ET * 2];
__device__ __align__(16) float g_denom[(size_t)NN * 2];
__device__ __align__(8)  int2  g_edge[(size_t)ET];
__device__ int g_is64;

// ---------------------------------------------------------------------------
// Detect whether edge_index buffer is int64 or int32.
// int64 little-endian nonnegative < 2^31: every odd 32-bit word is the high
// word == 0. For int32 data the odd words are random node ids in [0,50000);
// 256 consecutive zeros is impossible for the given random graph.
__global__ void k_detect(const int* __restrict__ ei) {
    if (threadIdx.x == 0 && blockIdx.x == 0) {
        int is64 = 1;
        for (int i = 0; i < 256; i++)
            if (ei[2 * i + 1] != 0) { is64 = 0; break; }
        g_is64 = is64;
    }
}

// Materialize (src,dst) int2 edge list incl. self loops, dtype-agnostic.
__global__ void k_build_edges(const int* __restrict__ ei32) {
    int e = blockIdx.x * blockDim.x + threadIdx.x;
    if (e >= ET) return;
    int s, d;
    if (e < EE) {
        if (g_is64) {
            const long long* p = (const long long*)ei32;
            s = (int)p[e];
            d = (int)p[(size_t)EE + e];
        } else {
            s = ei32[e];
            d = ei32[EE + e];
        }
    } else {
        s = e - EE; d = s;
    }
    g_edge[e] = make_int2(s, d);
}

// ---------------------------------------------------------------------------
// zero init: g_agg and g_denom
__global__ void k_zero_init() {
    int i = blockIdx.x * blockDim.x + threadIdx.x;
    if (i < NN * HC) g_agg[i] = 0.f;
    if (i < NN * 2)  g_denom[i] = 0.f;
}

// ---------------------------------------------------------------------------
// Dual SGEMM: out{L,R}[M,64] = X[M,KT] @ W{l,r}[KT,64] + b{l,r}
// blockIdx.y selects L (0) or R (1). BM=64, BN=64, BK=16, 256 thr, 4x4/thread.
template <int KT>
__global__ void k_gemm_dual(const float* __restrict__ X, int M,
                            const float* __restrict__ Wl, const float* __restrict__ bl,
                            const float* __restrict__ Wr, const float* __restrict__ br,
                            float* __restrict__ outL, float* __restrict__ outR) {
    const float* W    = blockIdx.y ? Wr : Wl;
    const float* bias = blockIdx.y ? br : bl;
    float* out        = blockIdx.y ? outR : outL;

    __shared__ float As[16][68];   // [k][m] transposed, padded
    __shared__ float Ws[16][64];   // [k][n]

    const int tid = threadIdx.x;
    const int m0 = blockIdx.x * 64;
    const int tx = tid & 15;       // col group (4 cols)
    const int ty = tid >> 4;       // row group (4 rows)

    float acc[4][4] = {};

    for (int kc = 0; kc < KT; kc += 16) {
        {
            int r  = tid >> 2;      // 0..63
            int c4 = tid & 3;       // 0..3
            int m  = m0 + r;
            float4 v = make_float4(0.f, 0.f, 0.f, 0.f);
            if (m < M) v = *(const float4*)(X + (size_t)m * KT + kc + c4 * 4);
            As[c4 * 4 + 0][r] = v.x;
            As[c4 * 4 + 1][r] = v.y;
            As[c4 * 4 + 2][r] = v.z;
            As[c4 * 4 + 3][r] = v.w;
        }
        {
            int k  = tid >> 4;      // 0..15
            int c4 = tid & 15;      // 0..15
            float4 w = *(const float4*)(W + (size_t)(kc + k) * 64 + c4 * 4);
            *(float4*)&Ws[k][c4 * 4] = w;
        }
        __syncthreads();
        #pragma unroll
        for (int kk = 0; kk < 16; kk++) {
            float4 a4 = *(const float4*)&As[kk][ty * 4];
            float4 w4 = *(const float4*)&Ws[kk][tx * 4];
            float av[4] = {a4.x, a4.y, a4.z, a4.w};
            float wv[4] = {w4.x, w4.y, w4.z, w4.w};
            #pragma unroll
            for (int i = 0; i < 4; i++)
                #pragma unroll
                for (int j = 0; j < 4; j++)
                    acc[i][j] += av[i] * wv[j];
        }
        __syncthreads();
    }

    float4 bv = *(const float4*)(bias + tx * 4);
    float bvv[4] = {bv.x, bv.y, bv.z, bv.w};
    #pragma unroll
    for (int i = 0; i < 4; i++) {
        int m = m0 + ty * 4 + i;
        if (m < M) {
            float4 r;
            r.x = acc[i][0] + bvv[0];
            r.y = acc[i][1] + bvv[1];
            r.z = acc[i][2] + bvv[2];
            r.w = acc[i][3] + bvv[3];
            *(float4*)(out + (size_t)m * 64 + tx * 4) = r;
        }
    }
}

// ---------------------------------------------------------------------------
// Edge pass A: alpha = att . leaky_relu(xl[src] + xr[dst]); ex = exp(alpha);
// atomic denom. 16 lanes per edge (lanes 0-7 head0, 8-15 head1).
__global__ void k_edge_alpha(const float* __restrict__ att) {
    int t = blockIdx.x * blockDim.x + threadIdx.x;
    int e = t >> 4;
    int g = t & 15;
    if (e >= ET) return;
    int2 ed = g_edge[e];
    int src = ed.x, dst = ed.y;

    float4 xl4 = *(const float4*)(g_xl + (size_t)src * 64 + g * 4);
    float4 xr4 = *(const float4*)(g_xr + (size_t)dst * 64 + g * 4);
    float m0 = xl4.x + xr4.x, m1 = xl4.y + xr4.y, m2 = xl4.z + xr4.z, m3 = xl4.w + xr4.w;
    m0 = m0 > 0.f ? m0 : 0.2f * m0;
    m1 = m1 > 0.f ? m1 : 0.2f * m1;
    m2 = m2 > 0.f ? m2 : 0.2f * m2;
    m3 = m3 > 0.f ? m3 : 0.2f * m3;

    int head = g >> 3;
    float4 a4 = *(const float4*)(att + head * 32 + (g & 7) * 4);
    float p = m0 * a4.x + m1 * a4.y + m2 * a4.z + m3 * a4.w;
    p += __shfl_xor_sync(0xffffffffu, p, 1);
    p += __shfl_xor_sync(0xffffffffu, p, 2);
    p += __shfl_xor_sync(0xffffffffu, p, 4);
    if ((g & 7) == 0) {
        float ex = __expf(p);
        g_ex[(size_t)e * 2 + head] = ex;
        atomicAdd(&g_denom[(size_t)dst * 2 + head], ex);
    }
}

// ---------------------------------------------------------------------------
// Edge pass B: a = ex/denom[dst]; agg[dst] += a * xl[src]  (float4 RED)
__global__ void k_edge_agg() {
    int t = blockIdx.x * blockDim.x + threadIdx.x;
    int e = t >> 4;
    int g = t & 15;
    if (e >= ET) return;
    int2 ed = g_edge[e];
    int src = ed.x, dst = ed.y;

    int head = g >> 3;
    float a = g_ex[(size_t)e * 2 + head] / g_denom[(size_t)dst * 2 + head];
    float4 xl4 = *(const float4*)(g_xl + (size_t)src * 64 + g * 4);
    float4 v;
    v.x = xl4.x * a; v.y = xl4.y * a; v.z = xl4.z * a; v.w = xl4.w * a;
    atomicAdd((float4*)(g_agg + (size_t)dst * 64 + g * 4), v);
}

// ---------------------------------------------------------------------------
// Between layers: h = relu(agg + b1); zero agg & denom for layer 2
__global__ void k_mid(const float* __restrict__ b1) {
    int i = blockIdx.x * blockDim.x + threadIdx.x;
    if (i < NN * HC) {
        float v = g_agg[i] + b1[i & 63];
        g_h[i] = v > 0.f ? v : 0.f;
        g_agg[i] = 0.f;
    }
    if (i < NN * 2) g_denom[i] = 0.f;
}

// ---------------------------------------------------------------------------
// Final head: bias2 + BN + relu -> emb (Wp,bp) -> risk head. Thread per node.
__global__ void k_final(const float* __restrict__ b2,
                        const float* __restrict__ bn_g, const float* __restrict__ bn_b,
                        const float* __restrict__ bn_m, const float* __restrict__ bn_v,
                        const float* __restrict__ Wp, const float* __restrict__ bp,
                        const float* __restrict__ Wh1, const float* __restrict__ bh1,
                        const float* __restrict__ Wh2, const float* __restrict__ bh2,
                        float* __restrict__ out) {
    int n = blockIdx.x * blockDim.x + threadIdx.x;
    if (n >= NN) return;

    float h[64];
    #pragma unroll
    for (int i = 0; i < 64; i++) {
        float v = g_agg[(size_t)n * 64 + i] + b2[i];
        v = (v - bn_m[i]) * rsqrtf(bn_v[i] + 1e-5f) * bn_g[i] + bn_b[i];
        h[i] = v > 0.f ? v : 0.f;
    }
    float emb[16];
    #pragma unroll
    for (int j = 0; j < 16; j++) emb[j] = bp[j];
    #pragma unroll
    for (int k = 0; k < 64; k++) {
        float hk = h[k];
        #pragma unroll
        for (int j = 0; j < 16; j++) emb[j] += hk * Wp[k * 16 + j];
    }
    #pragma unroll
    for (int j = 0; j < 16; j++) out[(size_t)n * 16 + j] = emb[j];

    float hid[8];
    #pragma unroll
    for (int j = 0; j < 8; j++) {
        float s = bh1[j];
        #pragma unroll
        for (int k = 0; k < 16; k++) s += emb[k] * Wh1[k * 8 + j];
        hid[j] = s > 0.f ? s : 0.f;
    }
    float risk = bh2[0];
    #pragma unroll
    for (int j = 0; j < 8; j++) risk += hid[j] * Wh2[j];
    out[(size_t)NN * 16 + n] = risk;
}

// ---------------------------------------------------------------------------
extern "C" void kernel_launch(void* const* d_in, const int* in_sizes, int n_in,
                              void* d_out, int out_size) {
    const float* x    = (const float*)d_in[0];
    const int*   ei   = (const int*)d_in[1];   // int32 or int64 — probed on device
    const float* Wl1  = (const float*)d_in[2];
    const float* bl1  = (const float*)d_in[3];
    const float* Wr1  = (const float*)d_in[4];
    const float* br1  = (const float*)d_in[5];
    const float* att1 = (const float*)d_in[6];
    const float* b1   = (const float*)d_in[7];
    const float* Wl2  = (const float*)d_in[8];
    const float* bl2  = (const float*)d_in[9];
    const float* Wr2  = (const float*)d_in[10];
    const float* br2  = (const float*)d_in[11];
    const float* att2 = (const float*)d_in[12];
    const float* b2   = (const float*)d_in[13];
    const float* bn_g = (const float*)d_in[14];
    const float* bn_b = (const float*)d_in[15];
    const float* bn_m = (const float*)d_in[16];
    const float* bn_v = (const float*)d_in[17];
    const float* Wp   = (const float*)d_in[18];
    const float* bp   = (const float*)d_in[19];
    const float* Wh1  = (const float*)d_in[20];
    const float* bh1  = (const float*)d_in[21];
    const float* Wh2  = (const float*)d_in[22];
    const float* bh2  = (const float*)d_in[23];
    float* out = (float*)d_out;

    float *p_xl, *p_xr, *p_h;
    cudaGetSymbolAddress((void**)&p_xl, g_xl);
    cudaGetSymbolAddress((void**)&p_xr, g_xr);
    cudaGetSymbolAddress((void**)&p_h,  g_h);

    const int ZB = (NN * HC + 255) / 256;
    const int GB = (NN + 63) / 64;
    const int EB = (ET * 16 + 255) / 256;
    const int BB = (ET + 255) / 256;

    k_detect<<<1, 32>>>(ei);
    k_build_edges<<<BB, 256>>>(ei);
    k_zero_init<<<ZB, 256>>>();
    k_gemm_dual<F_IN><<<dim3(GB, 2), 256>>>(x, NN, Wl1, bl1, Wr1, br1, p_xl, p_xr);
    k_edge_alpha<<<EB, 256>>>(att1);
    k_edge_agg<<<EB, 256>>>();
    k_mid<<<ZB, 256>>>(b1);
    k_gemm_dual<HC><<<dim3(GB, 2), 256>>>(p_h, NN, Wl2, bl2, Wr2, br2, p_xl, p_xr);
    k_edge_alpha<<<EB, 256>>>(att2);
    k_edge_agg<<<EB, 256>>>();
    k_final<<<(NN + 127) / 128, 128>>>(b2, bn_g, bn_b, bn_m, bn_v,
                                       Wp, bp, Wh1, bh1, Wh2, bh2, out);
}

// round 5
// speedup vs baseline: 1.1798x; 1.1798x over previous
#include <cuda_runtime.h>
#include <cuda_bf16.h>
#include <math.h>

#define NN 50000
#define EE 800000
#define ET (EE + NN)
#define HC 64
#define F_IN 128
#define OUTD 16

__device__ __align__(16) float g_xl[(size_t)NN * HC];
__device__ __align__(16) float g_xr[(size_t)NN * HC];
__device__ __align__(16) float g_h [(size_t)NN * HC];
__device__ __align__(16) float g_agg[(size_t)NN * HC];
__device__ __align__(16) float g_denom[2][(size_t)NN * 2];  // per-layer
__device__ __align__(8)  int2  g_edge[(size_t)ET];
__device__ int g_is64;

// ---------------------------------------------------------------------------
__global__ void k_detect(const int* __restrict__ ei) {
    if (threadIdx.x == 0 && blockIdx.x == 0) {
        int is64 = 1;
        for (int i = 0; i < 256; i++)
            if (ei[2 * i + 1] != 0) { is64 = 0; break; }
        g_is64 = is64;
    }
}

__global__ void k_build_edges(const int* __restrict__ ei32) {
    int e = blockIdx.x * blockDim.x + threadIdx.x;
    if (e >= ET) return;
    int s, d;
    if (e < EE) {
        if (g_is64) {
            const long long* p = (const long long*)ei32;
            s = (int)p[e];
            d = (int)p[(size_t)EE + e];
        } else {
            s = ei32[e];
            d = ei32[EE + e];
        }
    } else {
        s = e - EE; d = s;
    }
    g_edge[e] = make_int2(s, d);
}

// zero g_agg + both denom buffers
__global__ void k_zero_init() {
    int i = blockIdx.x * blockDim.x + threadIdx.x;
    if (i < NN * HC) g_agg[i] = 0.f;
    if (i < NN * 4)  ((float*)g_denom)[i] = 0.f;
}

// ---------------------------------------------------------------------------
// Dual SGEMM: out{L,R}[M,64] = X[M,KT] @ W{l,r}[KT,64] + b{l,r}
// BM=256, BN=64, BK=16, 256 threads, 8x8 per thread (LDS/FFMA balanced).
template <int KT>
__global__ void k_gemm_dual(const float* __restrict__ X, int M,
                            const float* __restrict__ Wl, const float* __restrict__ bl,
                            const float* __restrict__ Wr, const float* __restrict__ br,
                            float* __restrict__ outL, float* __restrict__ outR) {
    const float* W    = blockIdx.y ? Wr : Wl;
    const float* bias = blockIdx.y ? br : bl;
    float* out        = blockIdx.y ? outR : outL;

    __shared__ float As[16][264];   // [k][m] transposed, padded
    __shared__ float Ws[16][64];    // [k][n]

    const int tid = threadIdx.x;
    const int m0 = blockIdx.x * 256;
    const int tx = tid & 7;         // 8 col-groups of 8
    const int ty = tid >> 3;        // 32 row-groups of 8

    float acc[8][8] = {};

    for (int kc = 0; kc < KT; kc += 16) {
        // load X tile: 256 rows x 16 k. Each thread: 4 float4.
        {
            int r  = tid >> 2;      // 0..63
            int c4 = tid & 3;       // 0..3
            #pragma unroll
            for (int i = 0; i < 4; i++) {
                int row = r + 64 * i;
                int m = m0 + row;
                float4 v = make_float4(0.f, 0.f, 0.f, 0.f);
                if (m < M) v = *(const float4*)(X + (size_t)m * KT + kc + c4 * 4);
                As[c4 * 4 + 0][row] = v.x;
                As[c4 * 4 + 1][row] = v.y;
                As[c4 * 4 + 2][row] = v.z;
                As[c4 * 4 + 3][row] = v.w;
            }
        }
        // load W tile: 16 k x 64 cols
        {
            int k  = tid >> 4;      // 0..15
            int c4 = tid & 15;      // 0..15
            float4 w = *(const float4*)(W + (size_t)(kc + k) * 64 + c4 * 4);
            *(float4*)&Ws[k][c4 * 4] = w;
        }
        __syncthreads();
        #pragma unroll
        for (int kk = 0; kk < 16; kk++) {
            float a[8], b[8];
            *(float4*)&a[0] = *(const float4*)&As[kk][ty * 8];
            *(float4*)&a[4] = *(const float4*)&As[kk][ty * 8 + 4];
            *(float4*)&b[0] = *(const float4*)&Ws[kk][tx * 8];
            *(float4*)&b[4] = *(const float4*)&Ws[kk][tx * 8 + 4];
            #pragma unroll
            for (int i = 0; i < 8; i++)
                #pragma unroll
                for (int j = 0; j < 8; j++)
                    acc[i][j] += a[i] * b[j];
        }
        __syncthreads();
    }

    float bv[8];
    *(float4*)&bv[0] = *(const float4*)(bias + tx * 8);
    *(float4*)&bv[4] = *(const float4*)(bias + tx * 8 + 4);
    #pragma unroll
    for (int i = 0; i < 8; i++) {
        int m = m0 + ty * 8 + i;
        if (m < M) {
            float4 r0, r1;
            r0.x = acc[i][0] + bv[0]; r0.y = acc[i][1] + bv[1];
            r0.z = acc[i][2] + bv[2]; r0.w = acc[i][3] + bv[3];
            r1.x = acc[i][4] + bv[4]; r1.y = acc[i][5] + bv[5];
            r1.z = acc[i][6] + bv[6]; r1.w = acc[i][7] + bv[7];
            *(float4*)(out + (size_t)m * 64 + tx * 8)     = r0;
            *(float4*)(out + (size_t)m * 64 + tx * 8 + 4) = r1;
        }
    }
}

// ---------------------------------------------------------------------------
// Fused edge pass: p = att . leaky_relu(xl[src]+xr[dst]); ex = exp(p);
// denom[dst] += ex; agg[dst] += ex * xl[src].  16 lanes/edge, 2 heads.
__global__ void k_edge_fused(const float* __restrict__ att, int layer) {
    int t = blockIdx.x * blockDim.x + threadIdx.x;
    int e = t >> 4;
    int g = t & 15;
    if (e >= ET) return;
    int2 ed = g_edge[e];
    int src = ed.x, dst = ed.y;

    float4 xl4 = *(const float4*)(g_xl + (size_t)src * 64 + g * 4);
    float4 xr4 = *(const float4*)(g_xr + (size_t)dst * 64 + g * 4);
    float m0 = xl4.x + xr4.x, m1 = xl4.y + xr4.y, m2 = xl4.z + xr4.z, m3 = xl4.w + xr4.w;
    m0 = m0 > 0.f ? m0 : 0.2f * m0;
    m1 = m1 > 0.f ? m1 : 0.2f * m1;
    m2 = m2 > 0.f ? m2 : 0.2f * m2;
    m3 = m3 > 0.f ? m3 : 0.2f * m3;

    int head = g >> 3;
    float4 a4 = *(const float4*)(att + head * 32 + (g & 7) * 4);
    float p = m0 * a4.x + m1 * a4.y + m2 * a4.z + m3 * a4.w;
    p += __shfl_xor_sync(0xffffffffu, p, 1);
    p += __shfl_xor_sync(0xffffffffu, p, 2);
    p += __shfl_xor_sync(0xffffffffu, p, 4);   // all 8 lanes hold head sum

    float ex = __expf(p);
    if ((g & 7) == 0)
        atomicAdd(&g_denom[layer][(size_t)dst * 2 + head], ex);

    float4 v;
    v.x = xl4.x * ex; v.y = xl4.y * ex; v.z = xl4.z * ex; v.w = xl4.w * ex;
    atomicAdd((float4*)(g_agg + (size_t)dst * 64 + g * 4), v);
}

// ---------------------------------------------------------------------------
// Between layers: h = relu(agg/denom0 + b1); reset agg for layer 2.
__global__ void k_mid(const float* __restrict__ b1) {
    int i = blockIdx.x * blockDim.x + threadIdx.x;
    if (i >= NN * HC) return;
    int n = i >> 6, c = i & 63;
    float d = g_denom[0][(size_t)n * 2 + (c >> 5)];
    float v = g_agg[i] / d + b1[c];
    g_h[i] = v > 0.f ? v : 0.f;
    g_agg[i] = 0.f;
}

// ---------------------------------------------------------------------------
// Final head: normalize + b2 + BN + relu -> emb -> risk. Thread per node.
__global__ void k_final(const float* __restrict__ b2,
                        const float* __restrict__ bn_g, const float* __restrict__ bn_b,
                        const float* __restrict__ bn_m, const float* __restrict__ bn_v,
                        const float* __restrict__ Wp, const float* __restrict__ bp,
                        const float* __restrict__ Wh1, const float* __restrict__ bh1,
                        const float* __restrict__ Wh2, const float* __restrict__ bh2,
                        float* __restrict__ out) {
    int n = blockIdx.x * blockDim.x + threadIdx.x;
    if (n >= NN) return;

    float d0 = g_denom[1][(size_t)n * 2 + 0];
    float d1 = g_denom[1][(size_t)n * 2 + 1];
    float h[64];
    #pragma unroll
    for (int i = 0; i < 64; i++) {
        float v = g_agg[(size_t)n * 64 + i] / (i < 32 ? d0 : d1) + b2[i];
        v = (v - bn_m[i]) * rsqrtf(bn_v[i] + 1e-5f) * bn_g[i] + bn_b[i];
        h[i] = v > 0.f ? v : 0.f;
    }
    float emb[16];
    #pragma unroll
    for (int j = 0; j < 16; j++) emb[j] = bp[j];
    #pragma unroll
    for (int k = 0; k < 64; k++) {
        float hk = h[k];
        #pragma unroll
        for (int j = 0; j < 16; j++) emb[j] += hk * Wp[k * 16 + j];
    }
    #pragma unroll
    for (int j = 0; j < 16; j++) out[(size_t)n * 16 + j] = emb[j];

    float hid[8];
    #pragma unroll
    for (int j = 0; j < 8; j++) {
        float s = bh1[j];
        #pragma unroll
        for (int k = 0; k < 16; k++) s += emb[k] * Wh1[k * 8 + j];
        hid[j] = s > 0.f ? s : 0.f;
    }
    float risk = bh2[0];
    #pragma unroll
    for (int j = 0; j < 8; j++) risk += hid[j] * Wh2[j];
    out[(size_t)NN * 16 + n] = risk;
}

// ---------------------------------------------------------------------------
extern "C" void kernel_launch(void* const* d_in, const int* in_sizes, int n_in,
                              void* d_out, int out_size) {
    const float* x    = (const float*)d_in[0];
    const int*   ei   = (const int*)d_in[1];
    const float* Wl1  = (const float*)d_in[2];
    const float* bl1  = (const float*)d_in[3];
    const float* Wr1  = (const float*)d_in[4];
    const float* br1  = (const float*)d_in[5];
    const float* att1 = (const float*)d_in[6];
    const float* b1   = (const float*)d_in[7];
    const float* Wl2  = (const float*)d_in[8];
    const float* bl2  = (const float*)d_in[9];
    const float* Wr2  = (const float*)d_in[10];
    const float* br2  = (const float*)d_in[11];
    const float* att2 = (const float*)d_in[12];
    const float* b2   = (const float*)d_in[13];
    const float* bn_g = (const float*)d_in[14];
    const float* bn_b = (const float*)d_in[15];
    const float* bn_m = (const float*)d_in[16];
    const float* bn_v = (const float*)d_in[17];
    const float* Wp   = (const float*)d_in[18];
    const float* bp   = (const float*)d_in[19];
    const float* Wh1  = (const float*)d_in[20];
    const float* bh1  = (const float*)d_in[21];
    const float* Wh2  = (const float*)d_in[22];
    const float* bh2  = (const float*)d_in[23];
    float* out = (float*)d_out;

    float *p_xl, *p_xr, *p_h;
    cudaGetSymbolAddress((void**)&p_xl, g_xl);
    cudaGetSymbolAddress((void**)&p_xr, g_xr);
    cudaGetSymbolAddress((void**)&p_h,  g_h);

    const int ZB = (NN * HC + 255) / 256;
    const int GB = (NN + 255) / 256;
    const int EB = (ET * 16 + 255) / 256;
    const int BB = (ET + 255) / 256;

    k_detect<<<1, 32>>>(ei);
    k_build_edges<<<BB, 256>>>(ei);
    k_zero_init<<<ZB, 256>>>();
    k_gemm_dual<F_IN><<<dim3(GB, 2), 256>>>(x, NN, Wl1, bl1, Wr1, br1, p_xl, p_xr);
    k_edge_fused<<<EB, 256>>>(att1, 0);
    k_mid<<<ZB, 256>>>(b1);
    k_gemm_dual<HC><<<dim3(GB, 2), 256>>>(p_h, NN, Wl2, bl2, Wr2, br2, p_xl, p_xr);
    k_edge_fused<<<EB, 256>>>(att2, 1);
    k_final<<<(NN + 127) / 128, 128>>>(b2, bn_g, bn_b, bn_m, bn_v,
                                       Wp, bp, Wh1, bh1, Wh2, bh2, out);
}

// round 6
// speedup vs baseline: 1.4559x; 1.2340x over previous
#include <cuda_runtime.h>
#include <cuda_bf16.h>
#include <math.h>

#define NN 50000
#define EE 800000
#define ET (EE + NN)
#define HC 64
#define F_IN 128
#define OUTD 16

__device__ __align__(16) float g_xl[(size_t)NN * HC];
__device__ __align__(16) float g_xr[(size_t)NN * HC];
__device__ __align__(16) float g_agg[(size_t)NN * HC];
__device__ __align__(16) float g_denom[2][(size_t)NN * 2];  // per-layer
__device__ __align__(8)  int2  g_edge[(size_t)ET];
__device__ int g_is64;

// ---------------------------------------------------------------------------
__global__ void k_detect(const int* __restrict__ ei) {
    if (threadIdx.x == 0 && blockIdx.x == 0) {
        int is64 = 1;
        for (int i = 0; i < 256; i++)
            if (ei[2 * i + 1] != 0) { is64 = 0; break; }
        g_is64 = is64;
    }
}

__global__ void k_build_edges(const int* __restrict__ ei32) {
    int e = blockIdx.x * blockDim.x + threadIdx.x;
    if (e >= ET) return;
    int s, d;
    if (e < EE) {
        if (g_is64) {
            const long long* p = (const long long*)ei32;
            s = (int)p[e];
            d = (int)p[(size_t)EE + e];
        } else {
            s = ei32[e];
            d = ei32[EE + e];
        }
    } else {
        s = e - EE; d = s;
    }
    g_edge[e] = make_int2(s, d);
}

// zero g_agg + both denom buffers
__global__ void k_zero_init() {
    int i = blockIdx.x * blockDim.x + threadIdx.x;
    if (i < NN * HC) g_agg[i] = 0.f;
    if (i < NN * 4)  ((float*)g_denom)[i] = 0.f;
}

// ---------------------------------------------------------------------------
// Fused dual SGEMM: outL = act(X) @ Wl + bl, outR = act(X) @ Wr + br.
// BM=64, BN=64, BK=16, 256 threads, TM=TN=4, both outputs per block
// (shares the A tile -> 1.5 B LDS per MAC).
// NORM: input is g_agg; apply relu(v/denom + bprev) on the fly and reset
// the accumulator to zero (in-place k_mid fusion).
template <int KT, bool NORM>
__global__ void __launch_bounds__(256, 3)
k_gemm_fused(float* __restrict__ X,
             const float* __restrict__ Wl, const float* __restrict__ bl,
             const float* __restrict__ Wr, const float* __restrict__ br,
             const float* __restrict__ dn, const float* __restrict__ bprev,
             float* __restrict__ outL, float* __restrict__ outR) {
    __shared__ float As[16][68];
    __shared__ float WsL[16][64];
    __shared__ float WsR[16][64];

    const int tid = threadIdx.x;
    const int m0 = blockIdx.x * 64;
    const int tx = tid & 15;        // col group (4 cols)
    const int ty = tid >> 4;        // row group (4 rows)

    float accL[4][4] = {};
    float accR[4][4] = {};

    for (int kc = 0; kc < KT; kc += 16) {
        // A tile: 64 rows x 16 k, one float4 per thread
        {
            int r  = tid >> 2;      // 0..63
            int c4 = tid & 3;       // 0..3
            int m  = m0 + r;
            int c  = kc + c4 * 4;
            float4 v = make_float4(0.f, 0.f, 0.f, 0.f);
            if (m < NN) {
                float4* p = (float4*)(X + (size_t)m * KT + c);
                v = *p;
                if (NORM) {
                    float rd = 1.f / dn[(size_t)m * 2 + (c >> 5)];
                    v.x = v.x * rd + bprev[c + 0];
                    v.y = v.y * rd + bprev[c + 1];
                    v.z = v.z * rd + bprev[c + 2];
                    v.w = v.w * rd + bprev[c + 3];
                    v.x = v.x > 0.f ? v.x : 0.f;
                    v.y = v.y > 0.f ? v.y : 0.f;
                    v.z = v.z > 0.f ? v.z : 0.f;
                    v.w = v.w > 0.f ? v.w : 0.f;
                    *p = make_float4(0.f, 0.f, 0.f, 0.f);  // reset agg for layer 2
                }
            }
            As[c4 * 4 + 0][r] = v.x;
            As[c4 * 4 + 1][r] = v.y;
            As[c4 * 4 + 2][r] = v.z;
            As[c4 * 4 + 3][r] = v.w;
        }
        // W tiles: 16 k x 64 cols each
        {
            int k  = tid >> 4;      // 0..15
            int c4 = tid & 15;      // 0..15
            *(float4*)&WsL[k][c4 * 4] = *(const float4*)(Wl + (size_t)(kc + k) * 64 + c4 * 4);
            *(float4*)&WsR[k][c4 * 4] = *(const float4*)(Wr + (size_t)(kc + k) * 64 + c4 * 4);
        }
        __syncthreads();
        #pragma unroll
        for (int kk = 0; kk < 16; kk++) {
            float a[4], bL[4], bR[4];
            *(float4*)a  = *(const float4*)&As[kk][ty * 4];
            *(float4*)bL = *(const float4*)&WsL[kk][tx * 4];
            *(float4*)bR = *(const float4*)&WsR[kk][tx * 4];
            #pragma unroll
            for (int i = 0; i < 4; i++)
                #pragma unroll
                for (int j = 0; j < 4; j++) {
                    accL[i][j] += a[i] * bL[j];
                    accR[i][j] += a[i] * bR[j];
                }
        }
        __syncthreads();
    }

    float4 bvL = *(const float4*)(bl + tx * 4);
    float4 bvR = *(const float4*)(br + tx * 4);
    #pragma unroll
    for (int i = 0; i < 4; i++) {
        int m = m0 + ty * 4 + i;
        if (m < NN) {
            float4 r;
            r.x = accL[i][0] + bvL.x; r.y = accL[i][1] + bvL.y;
            r.z = accL[i][2] + bvL.z; r.w = accL[i][3] + bvL.w;
            *(float4*)(outL + (size_t)m * 64 + tx * 4) = r;
            r.x = accR[i][0] + bvR.x; r.y = accR[i][1] + bvR.y;
            r.z = accR[i][2] + bvR.z; r.w = accR[i][3] + bvR.w;
            *(float4*)(outR + (size_t)m * 64 + tx * 4) = r;
        }
    }
}

// ---------------------------------------------------------------------------
// Fused edge pass: p = att . leaky_relu(xl[src]+xr[dst]); ex = exp(p);
// denom[dst] += ex; agg[dst] += ex * xl[src].  16 lanes/edge, 2 heads.
__global__ void k_edge_fused(const float* __restrict__ att, int layer) {
    int t = blockIdx.x * blockDim.x + threadIdx.x;
    int e = t >> 4;
    int g = t & 15;
    if (e >= ET) return;
    int2 ed = g_edge[e];
    int src = ed.x, dst = ed.y;

    float4 xl4 = *(const float4*)(g_xl + (size_t)src * 64 + g * 4);
    float4 xr4 = *(const float4*)(g_xr + (size_t)dst * 64 + g * 4);
    float m0 = xl4.x + xr4.x, m1 = xl4.y + xr4.y, m2 = xl4.z + xr4.z, m3 = xl4.w + xr4.w;
    m0 = m0 > 0.f ? m0 : 0.2f * m0;
    m1 = m1 > 0.f ? m1 : 0.2f * m1;
    m2 = m2 > 0.f ? m2 : 0.2f * m2;
    m3 = m3 > 0.f ? m3 : 0.2f * m3;

    int head = g >> 3;
    float4 a4 = *(const float4*)(att + head * 32 + (g & 7) * 4);
    float p = m0 * a4.x + m1 * a4.y + m2 * a4.z + m3 * a4.w;
    p += __shfl_xor_sync(0xffffffffu, p, 1);
    p += __shfl_xor_sync(0xffffffffu, p, 2);
    p += __shfl_xor_sync(0xffffffffu, p, 4);   // all 8 lanes hold head sum

    float ex = __expf(p);
    if ((g & 7) == 0)
        atomicAdd(&g_denom[layer][(size_t)dst * 2 + head], ex);

    float4 v;
    v.x = xl4.x * ex; v.y = xl4.y * ex; v.z = xl4.z * ex; v.w = xl4.w * ex;
    atomicAdd((float4*)(g_agg + (size_t)dst * 64 + g * 4), v);
}

// ---------------------------------------------------------------------------
// Final head: normalize + b2 + BN + relu -> emb -> risk. Thread per node.
__global__ void k_final(const float* __restrict__ b2,
                        const float* __restrict__ bn_g, const float* __restrict__ bn_b,
                        const float* __restrict__ bn_m, const float* __restrict__ bn_v,
                        const float* __restrict__ Wp, const float* __restrict__ bp,
                        const float* __restrict__ Wh1, const float* __restrict__ bh1,
                        const float* __restrict__ Wh2, const float* __restrict__ bh2,
                        float* __restrict__ out) {
    int n = blockIdx.x * blockDim.x + threadIdx.x;
    if (n >= NN) return;

    float d0 = 1.f / g_denom[1][(size_t)n * 2 + 0];
    float d1 = 1.f / g_denom[1][(size_t)n * 2 + 1];
    float h[64];
    #pragma unroll
    for (int i = 0; i < 64; i++) {
        float v = g_agg[(size_t)n * 64 + i] * (i < 32 ? d0 : d1) + b2[i];
        v = (v - bn_m[i]) * rsqrtf(bn_v[i] + 1e-5f) * bn_g[i] + bn_b[i];
        h[i] = v > 0.f ? v : 0.f;
    }
    float emb[16];
    #pragma unroll
    for (int j = 0; j < 16; j++) emb[j] = bp[j];
    #pragma unroll
    for (int k = 0; k < 64; k++) {
        float hk = h[k];
        #pragma unroll
        for (int j = 0; j < 16; j++) emb[j] += hk * Wp[k * 16 + j];
    }
    #pragma unroll
    for (int j = 0; j < 16; j++) out[(size_t)n * 16 + j] = emb[j];

    float hid[8];
    #pragma unroll
    for (int j = 0; j < 8; j++) {
        float s = bh1[j];
        #pragma unroll
        for (int k = 0; k < 16; k++) s += emb[k] * Wh1[k * 8 + j];
        hid[j] = s > 0.f ? s : 0.f;
    }
    float risk = bh2[0];
    #pragma unroll
    for (int j = 0; j < 8; j++) risk += hid[j] * Wh2[j];
    out[(size_t)NN * 16 + n] = risk;
}

// ---------------------------------------------------------------------------
extern "C" void kernel_launch(void* const* d_in, const int* in_sizes, int n_in,
                              void* d_out, int out_size) {
    float*       x    = (float*)d_in[0];
    const int*   ei   = (const int*)d_in[1];
    const float* Wl1  = (const float*)d_in[2];
    const float* bl1  = (const float*)d_in[3];
    const float* Wr1  = (const float*)d_in[4];
    const float* br1  = (const float*)d_in[5];
    const float* att1 = (const float*)d_in[6];
    const float* b1   = (const float*)d_in[7];
    const float* Wl2  = (const float*)d_in[8];
    const float* bl2  = (const float*)d_in[9];
    const float* Wr2  = (const float*)d_in[10];
    const float* br2  = (const float*)d_in[11];
    const float* att2 = (const float*)d_in[12];
    const float* b2   = (const float*)d_in[13];
    const float* bn_g = (const float*)d_in[14];
    const float* bn_b = (const float*)d_in[15];
    const float* bn_m = (const float*)d_in[16];
    const float* bn_v = (const float*)d_in[17];
    const float* Wp   = (const float*)d_in[18];
    const float* bp   = (const float*)d_in[19];
    const float* Wh1  = (const float*)d_in[20];
    const float* bh1  = (const float*)d_in[21];
    const float* Wh2  = (const float*)d_in[22];
    const float* bh2  = (const float*)d_in[23];
    float* out = (float*)d_out;

    float *p_xl, *p_xr, *p_agg, *p_dn0;
    cudaGetSymbolAddress((void**)&p_xl, g_xl);
    cudaGetSymbolAddress((void**)&p_xr, g_xr);
    cudaGetSymbolAddress((void**)&p_agg, g_agg);
    cudaGetSymbolAddress((void**)&p_dn0, g_denom);

    const int ZB = (NN * HC + 255) / 256;
    const int GB = (NN + 63) / 64;
    const int EB = (ET * 16 + 255) / 256;
    const int BB = (ET + 255) / 256;

    k_detect<<<1, 32>>>(ei);
    k_build_edges<<<BB, 256>>>(ei);
    k_zero_init<<<ZB, 256>>>();
    k_gemm_fused<F_IN, false><<<GB, 256>>>(x, Wl1, bl1, Wr1, br1,
                                           nullptr, nullptr, p_xl, p_xr);
    k_edge_fused<<<EB, 256>>>(att1, 0);
    // layer-2 GEMM reads g_agg, normalizes (denom0, b1, relu) on the fly and
    // resets g_agg to zero in-place (fused k_mid)
    k_gemm_fused<HC, true><<<GB, 256>>>(p_agg, Wl2, bl2, Wr2, br2,
                                        p_dn0, b1, p_xl, p_xr);
    k_edge_fused<<<EB, 256>>>(att2, 1);
    k_final<<<(NN + 127) / 128, 128>>>(b2, bn_g, bn_b, bn_m, bn_v,
                                       Wp, bp, Wh1, bh1, Wh2, bh2, out);
}

// round 9
// speedup vs baseline: 1.6813x; 1.1548x over previous
#include <cuda_runtime.h>
#include <cuda_bf16.h>
#include <math.h>

#define NN 50000
#define EE 800000
#define ET (EE + NN)
#define HC 64
#define F_IN 128
#define OUTD 16

__device__ __align__(16) float g_xl[(size_t)NN * HC];
__device__ __align__(16) float g_xr[(size_t)NN * HC];
__device__ __align__(16) float g_h [(size_t)NN * HC];
__device__ __align__(16) float g_agg[(size_t)NN * HC];
__device__ int g_csrsrc[(size_t)ET];
__device__ int g_start[NN];
__device__ int g_cnt[NN];
__device__ int g_cur[NN];
__device__ int g_cursor;
__device__ int g_is64;

// ---------------------------------------------------------------------------
__global__ void k_detect(const int* __restrict__ ei) {
    if (threadIdx.x == 0 && blockIdx.x == 0) {
        int is64 = 1;
        for (int i = 0; i < 256; i++)
            if (ei[2 * i + 1] != 0) { is64 = 0; break; }
        g_is64 = is64;
    }
}

__global__ void k_reset() {
    int n = blockIdx.x * blockDim.x + threadIdx.x;
    if (n < NN) g_cnt[n] = 0;
    if (n == 0) g_cursor = 0;
}

__device__ __forceinline__ int edge_dst(const int* ei, int e) {
    if (e >= EE) return e - EE;
    return g_is64 ? (int)((const long long*)ei)[(size_t)EE + e] : ei[EE + e];
}
__device__ __forceinline__ int edge_src(const int* ei, int e) {
    if (e >= EE) return e - EE;
    return g_is64 ? (int)((const long long*)ei)[e] : ei[e];
}

__global__ void k_count(const int* __restrict__ ei) {
    int e = blockIdx.x * blockDim.x + threadIdx.x;
    if (e >= ET) return;
    atomicAdd(&g_cnt[edge_dst(ei, e)], 1);
}

// warp-aggregated ticket allocation of CSR row starts
__global__ void k_alloc() {
    int n = blockIdx.x * blockDim.x + threadIdx.x;
    int lane = threadIdx.x & 31;
    int c = (n < NN) ? g_cnt[n] : 0;
    int s = c;
    #pragma unroll
    for (int o = 1; o < 32; o <<= 1) {
        int v = __shfl_up_sync(0xffffffffu, s, o);
        if (lane >= o) s += v;
    }
    int total = __shfl_sync(0xffffffffu, s, 31);
    int base = 0;
    if (lane == 31) base = atomicAdd(&g_cursor, total);
    base = __shfl_sync(0xffffffffu, base, 31);
    if (n < NN) {
        int st = base + s - c;
        g_start[n] = st;
        g_cur[n] = st;
    }
}

__global__ void k_scatter(const int* __restrict__ ei) {
    int e = blockIdx.x * blockDim.x + threadIdx.x;
    if (e >= ET) return;
    int s = edge_src(ei, e);
    int d = edge_dst(ei, e);
    int pos = atomicAdd(&g_cur[d], 1);
    g_csrsrc[pos] = s;
}

// ---------------------------------------------------------------------------
// Fused dual SGEMM: outL = X @ Wl + bl, outR = X @ Wr + br (shared A tile).
// BM=64, BN=64, BK=16, 256 threads, TM=TN=4.
template <int KT>
__global__ void __launch_bounds__(256, 3)
k_gemm_fused(const float* __restrict__ X,
             const float* __restrict__ Wl, const float* __restrict__ bl,
             const float* __restrict__ Wr, const float* __restrict__ br,
             float* __restrict__ outL, float* __restrict__ outR) {
    __shared__ float As[16][68];
    __shared__ float WsL[16][64];
    __shared__ float WsR[16][64];

    const int tid = threadIdx.x;
    const int m0 = blockIdx.x * 64;
    const int tx = tid & 15;
    const int ty = tid >> 4;

    float accL[4][4] = {};
    float accR[4][4] = {};

    for (int kc = 0; kc < KT; kc += 16) {
        {
            int r  = tid >> 2;
            int c4 = tid & 3;
            int m  = m0 + r;
            float4 v = make_float4(0.f, 0.f, 0.f, 0.f);
            if (m < NN) v = *(const float4*)(X + (size_t)m * KT + kc + c4 * 4);
            As[c4 * 4 + 0][r] = v.x;
            As[c4 * 4 + 1][r] = v.y;
            As[c4 * 4 + 2][r] = v.z;
            As[c4 * 4 + 3][r] = v.w;
        }
        {
            int k  = tid >> 4;
            int c4 = tid & 15;
            *(float4*)&WsL[k][c4 * 4] = *(const float4*)(Wl + (size_t)(kc + k) * 64 + c4 * 4);
            *(float4*)&WsR[k][c4 * 4] = *(const float4*)(Wr + (size_t)(kc + k) * 64 + c4 * 4);
        }
        __syncthreads();
        #pragma unroll
        for (int kk = 0; kk < 16; kk++) {
            float a[4], bL[4], bR[4];
            *(float4*)a  = *(const float4*)&As[kk][ty * 4];
            *(float4*)bL = *(const float4*)&WsL[kk][tx * 4];
            *(float4*)bR = *(const float4*)&WsR[kk][tx * 4];
            #pragma unroll
            for (int i = 0; i < 4; i++)
                #pragma unroll
                for (int j = 0; j < 4; j++) {
                    accL[i][j] += a[i] * bL[j];
                    accR[i][j] += a[i] * bR[j];
                }
        }
        __syncthreads();
    }

    float4 bvL = *(const float4*)(bl + tx * 4);
    float4 bvR = *(const float4*)(br + tx * 4);
    #pragma unroll
    for (int i = 0; i < 4; i++) {
        int m = m0 + ty * 4 + i;
        if (m < NN) {
            float4 r;
            r.x = accL[i][0] + bvL.x; r.y = accL[i][1] + bvL.y;
            r.z = accL[i][2] + bvL.z; r.w = accL[i][3] + bvL.w;
            *(float4*)(outL + (size_t)m * 64 + tx * 4) = r;
            r.x = accR[i][0] + bvR.x; r.y = accR[i][1] + bvR.y;
            r.z = accR[i][2] + bvR.z; r.w = accR[i][3] + bvR.w;
            *(float4*)(outR + (size_t)m * 64 + tx * 4) = r;
        }
    }
}

// ---------------------------------------------------------------------------
// CSR edge pass: 16 lanes per destination node. Loop over incoming edges,
// accumulate Sum(ex) and Sum(ex*xl[src]) in registers, write normalized
// result once. LAYER 0: h = relu(v + b1) -> g_h. LAYER 1: v -> g_agg.
template <int LAYER>
__global__ void k_edge_csr(const float* __restrict__ att,
                           const float* __restrict__ bias) {
    int t = blockIdx.x * blockDim.x + threadIdx.x;
    int n = t >> 4;
    int g = t & 15;
    if (n >= NN) return;

    const int beg = g_start[n];
    const int cnt = g_cnt[n];
    const int lane = threadIdx.x & 31;
    const unsigned mask8 = 0xffu << (lane & 24);   // 8-lane head subgroup

    float4 xr4 = *(const float4*)(g_xr + (size_t)n * 64 + g * 4);
    int head = g >> 3;
    float4 a4 = *(const float4*)(att + head * 32 + (g & 7) * 4);

    float acc0 = 0.f, acc1 = 0.f, acc2 = 0.f, acc3 = 0.f, dn = 0.f;

    #pragma unroll 2
    for (int i = 0; i < cnt; i++) {
        int src = g_csrsrc[beg + i];
        float4 xl4 = *(const float4*)(g_xl + (size_t)src * 64 + g * 4);
        float m0 = xl4.x + xr4.x, m1 = xl4.y + xr4.y;
        float m2 = xl4.z + xr4.z, m3 = xl4.w + xr4.w;
        m0 = m0 > 0.f ? m0 : 0.2f * m0;
        m1 = m1 > 0.f ? m1 : 0.2f * m1;
        m2 = m2 > 0.f ? m2 : 0.2f * m2;
        m3 = m3 > 0.f ? m3 : 0.2f * m3;
        float p = m0 * a4.x + m1 * a4.y + m2 * a4.z + m3 * a4.w;
        p += __shfl_xor_sync(mask8, p, 1);
        p += __shfl_xor_sync(mask8, p, 2);
        p += __shfl_xor_sync(mask8, p, 4);
        float ex = __expf(p);
        dn += ex;
        acc0 += ex * xl4.x;
        acc1 += ex * xl4.y;
        acc2 += ex * xl4.z;
        acc3 += ex * xl4.w;
    }

    float r = 1.f / dn;
    int c = g * 4;
    float4 v;
    v.x = acc0 * r; v.y = acc1 * r; v.z = acc2 * r; v.w = acc3 * r;
    if (LAYER == 0) {
        v.x += bias[c + 0]; v.y += bias[c + 1];
        v.z += bias[c + 2]; v.w += bias[c + 3];
        v.x = v.x > 0.f ? v.x : 0.f;
        v.y = v.y > 0.f ? v.y : 0.f;
        v.z = v.z > 0.f ? v.z : 0.f;
        v.w = v.w > 0.f ? v.w : 0.f;
        *(float4*)(g_h + (size_t)n * 64 + c) = v;
    } else {
        *(float4*)(g_agg + (size_t)n * 64 + c) = v;
    }
}

// ---------------------------------------------------------------------------
// Final head: b2 + BN + relu -> emb (Wp,bp) -> risk. Thread per node.
__global__ void k_final(const float* __restrict__ b2,
                        const float* __restrict__ bn_g, const float* __restrict__ bn_b,
                        const float* __restrict__ bn_m, const float* __restrict__ bn_v,
                        const float* __restrict__ Wp, const float* __restrict__ bp,
                        const float* __restrict__ Wh1, const float* __restrict__ bh1,
                        const float* __restrict__ Wh2, const float* __restrict__ bh2,
                        float* __restrict__ out) {
    int n = blockIdx.x * blockDim.x + threadIdx.x;
    if (n >= NN) return;

    float h[64];
    #pragma unroll
    for (int i = 0; i < 64; i++) {
        float v = g_agg[(size_t)n * 64 + i] + b2[i];
        v = (v - bn_m[i]) * rsqrtf(bn_v[i] + 1e-5f) * bn_g[i] + bn_b[i];
        h[i] = v > 0.f ? v : 0.f;
    }
    float emb[16];
    #pragma unroll
    for (int j = 0; j < 16; j++) emb[j] = bp[j];
    #pragma unroll
    for (int k = 0; k < 64; k++) {
        float hk = h[k];
        #pragma unroll
        for (int j = 0; j < 16; j++) emb[j] += hk * Wp[k * 16 + j];
    }
    #pragma unroll
    for (int j = 0; j < 16; j++) out[(size_t)n * 16 + j] = emb[j];

    float hid[8];
    #pragma unroll
    for (int j = 0; j < 8; j++) {
        float s = bh1[j];
        #pragma unroll
        for (int k = 0; k < 16; k++) s += emb[k] * Wh1[k * 8 + j];
        hid[j] = s > 0.f ? s : 0.f;
    }
    float risk = bh2[0];
    #pragma unroll
    for (int j = 0; j < 8; j++) risk += hid[j] * Wh2[j];
    out[(size_t)NN * 16 + n] = risk;
}

// ---------------------------------------------------------------------------
extern "C" void kernel_launch(void* const* d_in, const int* in_sizes, int n_in,
                              void* d_out, int out_size) {
    const float* x    = (const float*)d_in[0];
    const int*   ei   = (const int*)d_in[1];
    const float* Wl1  = (const float*)d_in[2];
    const float* bl1  = (const float*)d_in[3];
    const float* Wr1  = (const float*)d_in[4];
    const float* br1  = (const float*)d_in[5];
    const float* att1 = (const float*)d_in[6];
    const float* b1   = (const float*)d_in[7];
    const float* Wl2  = (const float*)d_in[8];
    const float* bl2  = (const float*)d_in[9];
    const float* Wr2  = (const float*)d_in[10];
    const float* br2  = (const float*)d_in[11];
    const float* att2 = (const float*)d_in[12];
    const float* b2   = (const float*)d_in[13];
    const float* bn_g = (const float*)d_in[14];
    const float* bn_b = (const float*)d_in[15];
    const float* bn_m = (const float*)d_in[16];
    const float* bn_v = (const float*)d_in[17];
    const float* Wp   = (const float*)d_in[18];
    const float* bp   = (const float*)d_in[19];
    const float* Wh1  = (const float*)d_in[20];
    const float* bh1  = (const float*)d_in[21];
    const float* Wh2  = (const float*)d_in[22];
    const float* bh2  = (const float*)d_in[23];
    float* out = (float*)d_out;

    float *p_xl, *p_xr, *p_h;
    cudaGetSymbolAddress((void**)&p_xl, g_xl);
    cudaGetSymbolAddress((void**)&p_xr, g_xr);
    cudaGetSymbolAddress((void**)&p_h,  g_h);

    const int RB = (NN + 255) / 256;
    const int CB = (ET + 255) / 256;
    const int GB = (NN + 63) / 64;
    const int NB = (NN * 16 + 255) / 256;

    k_detect<<<1, 32>>>(ei);
    k_reset<<<RB, 256>>>();
    k_count<<<CB, 256>>>(ei);
    k_alloc<<<RB, 256>>>();
    k_scatter<<<CB, 256>>>(ei);
    k_gemm_fused<F_IN><<<GB, 256>>>(x, Wl1, bl1, Wr1, br1, p_xl, p_xr);
    k_edge_csr<0><<<NB, 256>>>(att1, b1);
    k_gemm_fused<HC><<<GB, 256>>>(p_h, Wl2, bl2, Wr2, br2, p_xl, p_xr);
    k_edge_csr<1><<<NB, 256>>>(att2, nullptr);
    k_final<<<(NN + 127) / 128, 128>>>(b2, bn_g, bn_b, bn_m, bn_v,
                                       Wp, bp, Wh1, bh1, Wh2, bh2, out);
}